// round 2
// baseline (speedup 1.0000x reference)
#include <cuda_runtime.h>
#include <cstdint>

// Problem constants (fixed shapes from reference setup_inputs)
#define B_TOT 1024
#define I_TOT 8
#define C_TOT 32
#define D_TOT 512
#define M_TOT 32
#define BT    32     // b-rows per block

// SMEM row strides (in 32-bit words). All chosen with stride % 32 == 8 (or
// benign) so the 8-row x 4-colpair fragment LDS.64 loads are conflict-free.
#define XS_LD 520
#define BS_LD 136
#define AS_LD 40
#define ST_LD 33
#define IN_LD 40

struct Smem {
  uint32_t xs[BT][XS_LD];        // X tile, tf32, within-8 permuted   (66560 B)
  uint32_t bs[2][M_TOT][BS_LD];  // B chunk double buffer             (34816 B)
  uint32_t as2[2][128][AS_LD];   // A chunk double buffer             (40960 B)
  float    stage[4][BT][ST_LD];  // GEMM1 K-split partial sums        (16896 B)
  uint32_t inr[BT][IN_LD];       // masked inner, tf32, permuted      ( 5120 B)
  float    maskf[BT];            // per-row mask for current C        (  128 B)
};                               // total 164480 B < 227 KB

__device__ __forceinline__ uint32_t f2tf(float f) {
  uint32_t u;
  asm("cvt.rna.tf32.f32 %0, %1;" : "=r"(u) : "f"(f));
  return u;
}

__device__ __forceinline__ void mma_tf32(float d[4], const uint32_t a[4],
                                         const uint32_t b[2]) {
  asm volatile(
      "mma.sync.aligned.m16n8k8.row.col.f32.tf32.tf32.f32 "
      "{%0,%1,%2,%3},{%4,%5,%6,%7},{%8,%9},{%0,%1,%2,%3};\n"
      : "+f"(d[0]), "+f"(d[1]), "+f"(d[2]), "+f"(d[3])
      : "r"(a[0]), "r"(a[1]), "r"(a[2]), "r"(a[3]), "r"(b[0]), "r"(b[1]));
}

// Store 8 consecutive logical floats (v0 = l0..l3, v1 = l4..l7) as tf32 with the
// within-8 permutation phys = {l0,l4,l1,l5,l2,l6,l3,l7}. This makes logical
// columns (c, c+4) physically adjacent so fragment loads are single LDS.64.
__device__ __forceinline__ void store_perm8(uint32_t* dst, float4 v0, float4 v1) {
  uint4 p0, p1;
  p0.x = f2tf(v0.x); p0.y = f2tf(v1.x); p0.z = f2tf(v0.y); p0.w = f2tf(v1.y);
  p1.x = f2tf(v0.z); p1.y = f2tf(v1.z); p1.z = f2tf(v0.w); p1.w = f2tf(v1.w);
  *reinterpret_cast<uint4*>(dst)     = p0;
  *reinterpret_cast<uint4*>(dst + 4) = p1;
}

__global__ void __launch_bounds__(256, 1)
tlc_kernel(const float* __restrict__ x, const int* __restrict__ topk,
           const float* __restrict__ Aw, const float* __restrict__ Bw,
           float* __restrict__ out) {
  extern __shared__ unsigned char smem_raw[];
  Smem& s = *reinterpret_cast<Smem*>(smem_raw);

  const int tid = threadIdx.x;
  const int i   = blockIdx.x >> 5;          // expert index 0..7
  const int b0  = (blockIdx.x & 31) * BT;   // b-tile start

  const int wid  = tid >> 5, lane = tid & 31;
  const int grp  = lane >> 2, qc = lane & 3;
  const int nh   = wid & 1,  kq = wid >> 1;   // GEMM1 roles: n-half, k-quarter
  const int mt2  = wid >> 2, ng = wid & 3;    // GEMM2 roles: m-tile, n-group

  // ---- Load X tile (32 x 512) once: fp32 -> tf32, permuted ----
  #pragma unroll
  for (int q = 0; q < 8; q++) {
    int idx = q * 256 + tid;
    int row = idx >> 6, g = idx & 63;
    const float* src = x + ((size_t)(b0 + row) * I_TOT + i) * D_TOT + g * 8;
    float4 v0 = *reinterpret_cast<const float4*>(src);
    float4 v1 = *reinterpret_cast<const float4*>(src + 4);
    store_perm8(&s.xs[row][g * 8], v0, v1);
  }

  // Output accumulators: this thread's share of out[32 x 512], fp32,
  // accumulated over all 32 components. 4 n-chunks x 4 n-tiles x 4 regs.
  float oacc[4][4][4];
  #pragma unroll
  for (int a = 0; a < 4; a++)
    #pragma unroll
    for (int b = 0; b < 4; b++)
      #pragma unroll
      for (int r = 0; r < 4; r++) oacc[a][b][r] = 0.f;

  const float* Bbase = Bw + (size_t)i * C_TOT * M_TOT * D_TOT;
  const float* Abase = Aw + (size_t)i * C_TOT * D_TOT * M_TOT;

  for (int c = 0; c < C_TOT; c++) {
    if (tid < BT)
      s.maskf[tid] =
          (float)__ldg(&topk[((size_t)(b0 + tid) * I_TOT + i) * C_TOT + c]);

    // Prefetch B chunk 0 -> buf 0
    #pragma unroll
    for (int q = 0; q < 2; q++) {
      int idx = q * 256 + tid;
      int row = idx >> 4, g = idx & 15;
      const float* src = Bbase + (size_t)row * D_TOT + g * 8;
      float4 v0 = *reinterpret_cast<const float4*>(src);
      float4 v1 = *reinterpret_cast<const float4*>(src + 4);
      store_perm8(&s.bs[0][row][g * 8], v0, v1);
    }

    float g1[2][2][4];
    #pragma unroll
    for (int mt = 0; mt < 2; mt++)
      #pragma unroll
      for (int nt = 0; nt < 2; nt++)
        #pragma unroll
        for (int r = 0; r < 4; r++) g1[mt][nt][r] = 0.f;

    __syncthreads();

    // ---- GEMM1: inner[32,32] = X[32,512] @ B_c[32,512]^T ----
    // Warp (nh, kq): m-tiles {0,1}, n-tiles {2nh, 2nh+1}, K quarter kq.
    #pragma unroll
    for (int ch = 0; ch < 4; ch++) {
      int buf = ch & 1;
      if (ch < 3) {  // prefetch next chunk into other buffer
        #pragma unroll
        for (int q = 0; q < 2; q++) {
          int idx = q * 256 + tid;
          int row = idx >> 4, g = idx & 15;
          const float* src = Bbase + (size_t)row * D_TOT + (ch + 1) * 128 + g * 8;
          float4 v0 = *reinterpret_cast<const float4*>(src);
          float4 v1 = *reinterpret_cast<const float4*>(src + 4);
          store_perm8(&s.bs[buf ^ 1][row][g * 8], v0, v1);
        }
      }
      #pragma unroll
      for (int st = 0; st < 4; st++) {
        int kb = kq * 32 + st * 8 + 2 * qc;
        uint32_t afr[2][4], bfr[2][2];
        #pragma unroll
        for (int mt = 0; mt < 2; mt++) {
          int r = mt * 16 + grp;
          uint2 lo = *reinterpret_cast<const uint2*>(&s.xs[r][ch * 128 + kb]);
          uint2 hi = *reinterpret_cast<const uint2*>(&s.xs[r + 8][ch * 128 + kb]);
          afr[mt][0] = lo.x; afr[mt][2] = lo.y;
          afr[mt][1] = hi.x; afr[mt][3] = hi.y;
        }
        #pragma unroll
        for (int nt = 0; nt < 2; nt++) {
          int r = (2 * nh + nt) * 8 + grp;
          uint2 bv = *reinterpret_cast<const uint2*>(&s.bs[buf][r][kb]);
          bfr[nt][0] = bv.x; bfr[nt][1] = bv.y;
        }
        #pragma unroll
        for (int mt = 0; mt < 2; mt++)
          #pragma unroll
          for (int nt = 0; nt < 2; nt++)
            mma_tf32(g1[mt][nt], afr[mt], bfr[nt]);
      }
      __syncthreads();
    }

    // Stage K-split partials
    #pragma unroll
    for (int mt = 0; mt < 2; mt++)
      #pragma unroll
      for (int nt = 0; nt < 2; nt++) {
        int rr  = mt * 16 + grp;
        int col = (2 * nh + nt) * 8 + 2 * qc;
        s.stage[kq][rr][col]         = g1[mt][nt][0];
        s.stage[kq][rr][col + 1]     = g1[mt][nt][1];
        s.stage[kq][rr + 8][col]     = g1[mt][nt][2];
        s.stage[kq][rr + 8][col + 1] = g1[mt][nt][3];
      }
    __syncthreads();

    // Reduce over K quarters, apply mask, requantize to tf32 (permuted)
    #pragma unroll
    for (int q = 0; q < 4; q++) {
      int idx = q * 256 + tid;
      int r = idx >> 5, col = idx & 31;
      float v = (s.stage[0][r][col] + s.stage[1][r][col] +
                 s.stage[2][r][col] + s.stage[3][r][col]) * s.maskf[r];
      int pc = (col & ~7) | ((col & 3) << 1) | ((col >> 2) & 1);
      s.inr[r][pc] = f2tf(v);
    }

    // Prefetch A chunk 0 -> buf 0 (overlaps with reduction of other threads)
    #pragma unroll
    for (int q = 0; q < 2; q++) {
      int idx = q * 256 + tid;
      int row = idx >> 2, g = idx & 3;
      const float* src = Abase + (size_t)row * M_TOT + g * 8;
      float4 v0 = *reinterpret_cast<const float4*>(src);
      float4 v1 = *reinterpret_cast<const float4*>(src + 4);
      store_perm8(&s.as2[0][row][g * 8], v0, v1);
    }
    __syncthreads();

    // ---- GEMM2: out[32,512] += inner[32,32] @ A_c[512,32]^T ----
    // Warp (mt2, ng): 16 rows x 32 cols per n-chunk. A-frags (inner) hoisted.
    uint32_t ia[4][4];
    #pragma unroll
    for (int st = 0; st < 4; st++) {
      int r   = mt2 * 16 + grp;
      int col = st * 8 + 2 * qc;
      uint2 lo = *reinterpret_cast<const uint2*>(&s.inr[r][col]);
      uint2 hi = *reinterpret_cast<const uint2*>(&s.inr[r + 8][col]);
      ia[st][0] = lo.x; ia[st][2] = lo.y;
      ia[st][1] = hi.x; ia[st][3] = hi.y;
    }

    #pragma unroll
    for (int nc2 = 0; nc2 < 4; nc2++) {
      int buf = nc2 & 1;
      if (nc2 < 3) {  // prefetch next A chunk
        #pragma unroll
        for (int q = 0; q < 2; q++) {
          int idx = q * 256 + tid;
          int row = idx >> 2, g = idx & 3;
          const float* src = Abase + (size_t)((nc2 + 1) * 128 + row) * M_TOT + g * 8;
          float4 v0 = *reinterpret_cast<const float4*>(src);
          float4 v1 = *reinterpret_cast<const float4*>(src + 4);
          store_perm8(&s.as2[buf ^ 1][row][g * 8], v0, v1);
        }
      }
      #pragma unroll
      for (int nt = 0; nt < 4; nt++) {
        int r = ng * 32 + nt * 8 + grp;
        #pragma unroll
        for (int st = 0; st < 4; st++) {
          uint2 bv = *reinterpret_cast<const uint2*>(&s.as2[buf][r][st * 8 + 2 * qc]);
          uint32_t bb[2] = { bv.x, bv.y };
          mma_tf32(oacc[nc2][nt], ia[st], bb);
        }
      }
      __syncthreads();
    }

    Bbase += (size_t)M_TOT * D_TOT;
    Abase += (size_t)D_TOT * M_TOT;
  }  // component loop

  // ---- Epilogue: write out (covers every (b0..b0+31, i, 0..511) exactly once)
  #pragma unroll
  for (int nc2 = 0; nc2 < 4; nc2++)
    #pragma unroll
    for (int nt = 0; nt < 4; nt++) {
      int col = nc2 * 128 + ng * 32 + nt * 8 + 2 * qc;
      int r   = b0 + mt2 * 16 + grp;
      float2 v0 = make_float2(oacc[nc2][nt][0], oacc[nc2][nt][1]);
      float2 v1 = make_float2(oacc[nc2][nt][2], oacc[nc2][nt][3]);
      *reinterpret_cast<float2*>(out + ((size_t)r * I_TOT + i) * D_TOT + col) = v0;
      *reinterpret_cast<float2*>(out + ((size_t)(r + 8) * I_TOT + i) * D_TOT + col) = v1;
    }
}

extern "C" void kernel_launch(void* const* d_in, const int* in_sizes, int n_in,
                              void* d_out, int out_size) {
  const float* x    = (const float*)d_in[0];
  const int*   topk = (const int*)d_in[1];
  const float* Aw   = (const float*)d_in[2];  // original_A [i,C,d_out,m]
  const float* Bw   = (const float*)d_in[3];  // original_B [i,C,m,d_in]
  float*       out  = (float*)d_out;

  cudaFuncSetAttribute(tlc_kernel, cudaFuncAttributeMaxDynamicSharedMemorySize,
                       (int)sizeof(Smem));
  tlc_kernel<<<(B_TOT / BT) * I_TOT, 256, sizeof(Smem)>>>(x, topk, Aw, Bw, out);
}

// round 3
// speedup vs baseline: 1.0015x; 1.0015x over previous
#include <cuda_runtime.h>
#include <cstdint>

// Problem constants (fixed shapes from reference setup_inputs)
#define B_TOT 1024
#define I_TOT 8
#define C_TOT 32
#define D_TOT 512
#define M_TOT 32
#define BT    32     // b-rows per block

// SMEM row strides (in 32-bit words). All chosen with stride % 32 == 8 (or
// benign) so the 8-row x 4-colpair fragment LDS.64 loads are conflict-free.
#define XS_LD 520
#define BS_LD 136
#define AS_LD 40
#define ST_LD 33
#define IN_LD 40

struct Smem {
  uint32_t xs[BT][XS_LD];        // X tile, tf32, within-8 permuted   (66560 B)
  uint32_t bs[2][M_TOT][BS_LD];  // B chunk double buffer             (34816 B)
  uint32_t as2[2][128][AS_LD];   // A chunk double buffer             (40960 B)
  float    stage[4][BT][ST_LD];  // GEMM1 K-split partial sums        (16896 B)
  uint32_t inr[BT][IN_LD];       // masked inner, tf32, permuted      ( 5120 B)
  float    maskf[BT];            // per-row mask for current C        (  128 B)
};                               // total 164480 B < 227 KB

__device__ __forceinline__ uint32_t f2tf(float f) {
  uint32_t u;
  asm("cvt.rna.tf32.f32 %0, %1;" : "=r"(u) : "f"(f));
  return u;
}

__device__ __forceinline__ void mma_tf32(float d[4], const uint32_t a[4],
                                         const uint32_t b[2]) {
  asm volatile(
      "mma.sync.aligned.m16n8k8.row.col.f32.tf32.tf32.f32 "
      "{%0,%1,%2,%3},{%4,%5,%6,%7},{%8,%9},{%0,%1,%2,%3};\n"
      : "+f"(d[0]), "+f"(d[1]), "+f"(d[2]), "+f"(d[3])
      : "r"(a[0]), "r"(a[1]), "r"(a[2]), "r"(a[3]), "r"(b[0]), "r"(b[1]));
}

// Store 8 consecutive logical floats (v0 = l0..l3, v1 = l4..l7) as tf32 with the
// within-8 permutation phys = {l0,l4,l1,l5,l2,l6,l3,l7}. This makes logical
// columns (c, c+4) physically adjacent so fragment loads are single LDS.64.
__device__ __forceinline__ void store_perm8(uint32_t* dst, float4 v0, float4 v1) {
  uint4 p0, p1;
  p0.x = f2tf(v0.x); p0.y = f2tf(v1.x); p0.z = f2tf(v0.y); p0.w = f2tf(v1.y);
  p1.x = f2tf(v0.z); p1.y = f2tf(v1.z); p1.z = f2tf(v0.w); p1.w = f2tf(v1.w);
  *reinterpret_cast<uint4*>(dst)     = p0;
  *reinterpret_cast<uint4*>(dst + 4) = p1;
}

__global__ void __launch_bounds__(256, 1)
tlc_kernel(const float* __restrict__ x, const int* __restrict__ topk,
           const float* __restrict__ Aw, const float* __restrict__ Bw,
           float* __restrict__ out) {
  extern __shared__ unsigned char smem_raw[];
  Smem& s = *reinterpret_cast<Smem*>(smem_raw);

  const int tid = threadIdx.x;
  const int i   = blockIdx.x >> 5;          // expert index 0..7
  const int b0  = (blockIdx.x & 31) * BT;   // b-tile start

  const int wid  = tid >> 5, lane = tid & 31;
  const int grp  = lane >> 2, qc = lane & 3;
  const int nh   = wid & 1,  kq = wid >> 1;   // GEMM1 roles: n-half, k-quarter
  const int mt2  = wid >> 2, ng = wid & 3;    // GEMM2 roles: m-tile, n-group

  // ---- Load X tile (32 x 512) once: fp32 -> tf32, permuted ----
  #pragma unroll
  for (int q = 0; q < 8; q++) {
    int idx = q * 256 + tid;
    int row = idx >> 6, g = idx & 63;
    const float* src = x + ((size_t)(b0 + row) * I_TOT + i) * D_TOT + g * 8;
    float4 v0 = *reinterpret_cast<const float4*>(src);
    float4 v1 = *reinterpret_cast<const float4*>(src + 4);
    store_perm8(&s.xs[row][g * 8], v0, v1);
  }

  // Output accumulators: this thread's share of out[32 x 512], fp32,
  // accumulated over all 32 components. 4 n-chunks x 4 n-tiles x 4 regs.
  float oacc[4][4][4];
  #pragma unroll
  for (int a = 0; a < 4; a++)
    #pragma unroll
    for (int b = 0; b < 4; b++)
      #pragma unroll
      for (int r = 0; r < 4; r++) oacc[a][b][r] = 0.f;

  const float* Bbase = Bw + (size_t)i * C_TOT * M_TOT * D_TOT;
  const float* Abase = Aw + (size_t)i * C_TOT * D_TOT * M_TOT;

  for (int c = 0; c < C_TOT; c++) {
    if (tid < BT)
      s.maskf[tid] =
          (float)__ldg(&topk[((size_t)(b0 + tid) * I_TOT + i) * C_TOT + c]);

    // Prefetch B chunk 0 -> buf 0
    #pragma unroll
    for (int q = 0; q < 2; q++) {
      int idx = q * 256 + tid;
      int row = idx >> 4, g = idx & 15;
      const float* src = Bbase + (size_t)row * D_TOT + g * 8;
      float4 v0 = *reinterpret_cast<const float4*>(src);
      float4 v1 = *reinterpret_cast<const float4*>(src + 4);
      store_perm8(&s.bs[0][row][g * 8], v0, v1);
    }

    float g1[2][2][4];
    #pragma unroll
    for (int mt = 0; mt < 2; mt++)
      #pragma unroll
      for (int nt = 0; nt < 2; nt++)
        #pragma unroll
        for (int r = 0; r < 4; r++) g1[mt][nt][r] = 0.f;

    __syncthreads();

    // ---- GEMM1: inner[32,32] = X[32,512] @ B_c[32,512]^T ----
    // Warp (nh, kq): m-tiles {0,1}, n-tiles {2nh, 2nh+1}, K quarter kq.
    #pragma unroll
    for (int ch = 0; ch < 4; ch++) {
      int buf = ch & 1;
      if (ch < 3) {  // prefetch next chunk into other buffer
        #pragma unroll
        for (int q = 0; q < 2; q++) {
          int idx = q * 256 + tid;
          int row = idx >> 4, g = idx & 15;
          const float* src = Bbase + (size_t)row * D_TOT + (ch + 1) * 128 + g * 8;
          float4 v0 = *reinterpret_cast<const float4*>(src);
          float4 v1 = *reinterpret_cast<const float4*>(src + 4);
          store_perm8(&s.bs[buf ^ 1][row][g * 8], v0, v1);
        }
      }
      #pragma unroll
      for (int st = 0; st < 4; st++) {
        int kb = kq * 32 + st * 8 + 2 * qc;
        uint32_t afr[2][4], bfr[2][2];
        #pragma unroll
        for (int mt = 0; mt < 2; mt++) {
          int r = mt * 16 + grp;
          uint2 lo = *reinterpret_cast<const uint2*>(&s.xs[r][ch * 128 + kb]);
          uint2 hi = *reinterpret_cast<const uint2*>(&s.xs[r + 8][ch * 128 + kb]);
          afr[mt][0] = lo.x; afr[mt][2] = lo.y;
          afr[mt][1] = hi.x; afr[mt][3] = hi.y;
        }
        #pragma unroll
        for (int nt = 0; nt < 2; nt++) {
          int r = (2 * nh + nt) * 8 + grp;
          uint2 bv = *reinterpret_cast<const uint2*>(&s.bs[buf][r][kb]);
          bfr[nt][0] = bv.x; bfr[nt][1] = bv.y;
        }
        #pragma unroll
        for (int mt = 0; mt < 2; mt++)
          #pragma unroll
          for (int nt = 0; nt < 2; nt++)
            mma_tf32(g1[mt][nt], afr[mt], bfr[nt]);
      }
      __syncthreads();
    }

    // Stage K-split partials
    #pragma unroll
    for (int mt = 0; mt < 2; mt++)
      #pragma unroll
      for (int nt = 0; nt < 2; nt++) {
        int rr  = mt * 16 + grp;
        int col = (2 * nh + nt) * 8 + 2 * qc;
        s.stage[kq][rr][col]         = g1[mt][nt][0];
        s.stage[kq][rr][col + 1]     = g1[mt][nt][1];
        s.stage[kq][rr + 8][col]     = g1[mt][nt][2];
        s.stage[kq][rr + 8][col + 1] = g1[mt][nt][3];
      }
    __syncthreads();

    // Reduce over K quarters, apply mask, requantize to tf32 (permuted)
    #pragma unroll
    for (int q = 0; q < 4; q++) {
      int idx = q * 256 + tid;
      int r = idx >> 5, col = idx & 31;
      float v = (s.stage[0][r][col] + s.stage[1][r][col] +
                 s.stage[2][r][col] + s.stage[3][r][col]) * s.maskf[r];
      int pc = (col & ~7) | ((col & 3) << 1) | ((col >> 2) & 1);
      s.inr[r][pc] = f2tf(v);
    }

    // Prefetch A chunk 0 -> buf 0 (overlaps with reduction of other threads)
    #pragma unroll
    for (int q = 0; q < 2; q++) {
      int idx = q * 256 + tid;
      int row = idx >> 2, g = idx & 3;
      const float* src = Abase + (size_t)row * M_TOT + g * 8;
      float4 v0 = *reinterpret_cast<const float4*>(src);
      float4 v1 = *reinterpret_cast<const float4*>(src + 4);
      store_perm8(&s.as2[0][row][g * 8], v0, v1);
    }
    __syncthreads();

    // ---- GEMM2: out[32,512] += inner[32,32] @ A_c[512,32]^T ----
    // Warp (mt2, ng): 16 rows x 32 cols per n-chunk. A-frags (inner) hoisted.
    uint32_t ia[4][4];
    #pragma unroll
    for (int st = 0; st < 4; st++) {
      int r   = mt2 * 16 + grp;
      int col = st * 8 + 2 * qc;
      uint2 lo = *reinterpret_cast<const uint2*>(&s.inr[r][col]);
      uint2 hi = *reinterpret_cast<const uint2*>(&s.inr[r + 8][col]);
      ia[st][0] = lo.x; ia[st][2] = lo.y;
      ia[st][1] = hi.x; ia[st][3] = hi.y;
    }

    #pragma unroll
    for (int nc2 = 0; nc2 < 4; nc2++) {
      int buf = nc2 & 1;
      if (nc2 < 3) {  // prefetch next A chunk
        #pragma unroll
        for (int q = 0; q < 2; q++) {
          int idx = q * 256 + tid;
          int row = idx >> 2, g = idx & 3;
          const float* src = Abase + (size_t)((nc2 + 1) * 128 + row) * M_TOT + g * 8;
          float4 v0 = *reinterpret_cast<const float4*>(src);
          float4 v1 = *reinterpret_cast<const float4*>(src + 4);
          store_perm8(&s.as2[buf ^ 1][row][g * 8], v0, v1);
        }
      }
      #pragma unroll
      for (int nt = 0; nt < 4; nt++) {
        int r = ng * 32 + nt * 8 + grp;
        #pragma unroll
        for (int st = 0; st < 4; st++) {
          uint2 bv = *reinterpret_cast<const uint2*>(&s.as2[buf][r][st * 8 + 2 * qc]);
          uint32_t bb[2] = { bv.x, bv.y };
          mma_tf32(oacc[nc2][nt], ia[st], bb);
        }
      }
      __syncthreads();
    }

    Bbase += (size_t)M_TOT * D_TOT;
    Abase += (size_t)D_TOT * M_TOT;
  }  // component loop

  // ---- Epilogue: write out (covers every (b0..b0+31, i, 0..511) exactly once)
  #pragma unroll
  for (int nc2 = 0; nc2 < 4; nc2++)
    #pragma unroll
    for (int nt = 0; nt < 4; nt++) {
      int col = nc2 * 128 + ng * 32 + nt * 8 + 2 * qc;
      int r   = b0 + mt2 * 16 + grp;
      float2 v0 = make_float2(oacc[nc2][nt][0], oacc[nc2][nt][1]);
      float2 v1 = make_float2(oacc[nc2][nt][2], oacc[nc2][nt][3]);
      *reinterpret_cast<float2*>(out + ((size_t)r * I_TOT + i) * D_TOT + col) = v0;
      *reinterpret_cast<float2*>(out + ((size_t)(r + 8) * I_TOT + i) * D_TOT + col) = v1;
    }
}

extern "C" void kernel_launch(void* const* d_in, const int* in_sizes, int n_in,
                              void* d_out, int out_size) {
  const float* x    = (const float*)d_in[0];
  const int*   topk = (const int*)d_in[1];
  const float* Aw   = (const float*)d_in[2];  // original_A [i,C,d_out,m]
  const float* Bw   = (const float*)d_in[3];  // original_B [i,C,m,d_in]
  float*       out  = (float*)d_out;

  cudaFuncSetAttribute(tlc_kernel, cudaFuncAttributeMaxDynamicSharedMemorySize,
                       (int)sizeof(Smem));
  tlc_kernel<<<(B_TOT / BT) * I_TOT, 256, sizeof(Smem)>>>(x, topk, Aw, Bw, out);
}